// round 1
// baseline (speedup 1.0000x reference)
#include <cuda_runtime.h>

#define BN_EPS 1e-5f
#define Bz 8
#define Cz 256
#define Hz 128
#define Wz 128
#define HWz 16384

// Scratch (no allocations allowed -> device globals)
__device__ float d_masks[Bz][2][HWz];      // er, di
__device__ float d_mid[Bz][3][Cz];         // mid[b,k,c]
__device__ float d_Wfin[Bz][Cz * Cz];      // effective per-batch weight
__device__ float d_bfin[Bz][Cz];           // effective per-batch bias

// ---------------------------------------------------------------------------
// K1: threshold + 4x4 erosion/dilation (SAME, pad lo=1 hi=2, border-neutral)
// ---------------------------------------------------------------------------
__global__ void k_masks(const float* __restrict__ m) {
    int b = blockIdx.x;
    __shared__ unsigned char z[HWz];
    const float* mb = m + (size_t)b * HWz;
    for (int i = threadIdx.x; i < HWz; i += blockDim.x)
        z[i] = (fmaxf(mb[i], 0.0f) > 0.3f) ? 1 : 0;
    __syncthreads();
    for (int i = threadIdx.x; i < HWz; i += blockDim.x) {
        int h = i >> 7, w = i & 127;
        int er = 1, di = 0;
        #pragma unroll
        for (int dh = -1; dh <= 2; dh++) {
            int hh = h + dh;
            if (hh < 0 || hh >= Hz) continue;   // OOB neutral: pad 1 for min, 0 for max
            #pragma unroll
            for (int dw = -1; dw <= 2; dw++) {
                int ww = w + dw;
                if (ww < 0 || ww >= Wz) continue;
                int v = z[(hh << 7) + ww];
                er &= v; di |= v;
            }
        }
        d_masks[b][0][i] = (float)er;
        d_masks[b][1][i] = (float)di;
    }
}

// ---------------------------------------------------------------------------
// K2: mid[b,k,c] = sum_n fbu[b,k,n]*f[b,c,n]
//     fbu = [er, 1-di, di-er]  ->  mid0=dot(er,f), mid1=sum(f)-dot(di,f),
//                                  mid2=dot(di,f)-dot(er,f)
// ---------------------------------------------------------------------------
__global__ void k_mid(const float* __restrict__ feature) {
    int c = blockIdx.x, b = blockIdx.y;
    const float4* f  = (const float4*)(feature + ((size_t)b * Cz + c) * HWz);
    const float4* er = (const float4*)d_masks[b][0];
    const float4* di = (const float4*)d_masks[b][1];
    float ae = 0.f, ad = 0.f, as = 0.f;
    for (int i = threadIdx.x; i < HWz / 4; i += blockDim.x) {
        float4 fv = f[i], ev = er[i], dv = di[i];
        ae += fv.x * ev.x + fv.y * ev.y + fv.z * ev.z + fv.w * ev.w;
        ad += fv.x * dv.x + fv.y * dv.y + fv.z * dv.z + fv.w * dv.w;
        as += fv.x + fv.y + fv.z + fv.w;
    }
    // warp + block reduce
    #pragma unroll
    for (int off = 16; off; off >>= 1) {
        ae += __shfl_down_sync(0xffffffffu, ae, off);
        ad += __shfl_down_sync(0xffffffffu, ad, off);
        as += __shfl_down_sync(0xffffffffu, as, off);
    }
    __shared__ float red[3][8];
    int lane = threadIdx.x & 31, wid = threadIdx.x >> 5;
    if (lane == 0) { red[0][wid] = ae; red[1][wid] = ad; red[2][wid] = as; }
    __syncthreads();
    if (threadIdx.x == 0) {
        float e = 0.f, d = 0.f, s = 0.f;
        #pragma unroll
        for (int i = 0; i < 8; i++) { e += red[0][i]; d += red[1][i]; s += red[2][i]; }
        d_mid[b][0][c] = e;
        d_mid[b][1][c] = s - d;
        d_mid[b][2][c] = d - e;
    }
}

// ---------------------------------------------------------------------------
// K3: build per-batch effective weight/bias.
//   sf = gamma_f*rsqrt(var_f+eps); shf = beta_f - mean_f*sf  (same for _o)
//   v[k][c]    = sum_o mid[k][o]*sf[o]*w_feat[o,c]
//   const[k]   = sum_o mid[k][o]*shf[o]
//   W2M[o][k]  = sum_c w_out[o,256+c]*mid[k][c]
//   Wfin[o][c] = so[o]*(w_out[o,c] + sum_k W2M[o][k]*v[k][c])
//   bfin[o]    = so[o]*sum_k W2M[o][k]*const[k] + sho[o]
// ---------------------------------------------------------------------------
__global__ void k_prep(const float* __restrict__ w_feat,
                       const float* __restrict__ gf, const float* __restrict__ bf,
                       const float* __restrict__ mf, const float* __restrict__ vf,
                       const float* __restrict__ w_out,
                       const float* __restrict__ go, const float* __restrict__ bo,
                       const float* __restrict__ mo, const float* __restrict__ vo) {
    int b = blockIdx.x, t = threadIdx.x;  // 256 threads
    __shared__ float midS[3][Cz], vS[3][Cz], w2m[Cz][3];
    __shared__ float sfS[Cz], shfS[Cz], soS[Cz], constS[3];

    #pragma unroll
    for (int k = 0; k < 3; k++) midS[k][t] = d_mid[b][k][t];
    float sf = gf[t] * rsqrtf(vf[t] + BN_EPS);
    sfS[t] = sf;
    shfS[t] = bf[t] - mf[t] * sf;
    float so = go[t] * rsqrtf(vo[t] + BN_EPS);
    soS[t] = so;
    float sho = bo[t] - mo[t] * so;
    __syncthreads();

    // v[k][c], thread t = c  (coalesced w_feat column reads)
    {
        float v0 = 0.f, v1 = 0.f, v2 = 0.f;
        for (int o = 0; o < Cz; o++) {
            float w = w_feat[o * Cz + t] * sfS[o];
            v0 += midS[0][o] * w;
            v1 += midS[1][o] * w;
            v2 += midS[2][o] * w;
        }
        vS[0][t] = v0; vS[1][t] = v1; vS[2][t] = v2;
    }
    if (t < 3) {
        float cs = 0.f;
        for (int o = 0; o < Cz; o++) cs += midS[t][o] * shfS[o];
        constS[t] = cs;
    }
    // W2M, thread t = o
    {
        float a0 = 0.f, a1 = 0.f, a2 = 0.f;
        const float* wr = w_out + (size_t)t * (2 * Cz) + Cz;
        for (int c = 0; c < Cz; c++) {
            float w = wr[c];
            a0 += w * midS[0][c];
            a1 += w * midS[1][c];
            a2 += w * midS[2][c];
        }
        w2m[t][0] = a0; w2m[t][1] = a1; w2m[t][2] = a2;
    }
    __syncthreads();

    d_bfin[b][t] = so * (w2m[t][0] * constS[0] + w2m[t][1] * constS[1] +
                         w2m[t][2] * constS[2]) + sho;

    for (int i = t; i < Cz * Cz; i += 256) {
        int o = i >> 8, c = i & 255;
        float val = w_out[(size_t)o * (2 * Cz) + c]
                  + w2m[o][0] * vS[0][c] + w2m[o][1] * vS[1][c] + w2m[o][2] * vS[2][c];
        d_Wfin[b][i] = soS[o] * val;
    }
}

// ---------------------------------------------------------------------------
// K4: out[b] = Wfin[b] (256x256) @ feature[b] (256x16384) + bfin[b]
//     64x64 tile, BK=16, 4x4 per thread, 256 threads
// ---------------------------------------------------------------------------
__global__ __launch_bounds__(256) void k_gemm(const float* __restrict__ feature,
                                              float* __restrict__ out) {
    const int b  = blockIdx.z;
    const int bm = blockIdx.y * 64;
    const int bn = blockIdx.x * 64;
    __shared__ float As[16][64];   // [k][m]
    __shared__ float Bs[16][64];   // [k][n]
    const float* A  = d_Wfin[b];
    const float* Bm = feature + (size_t)b * Cz * HWz;
    float*       Cm = out + (size_t)b * Cz * HWz;

    int tid = threadIdx.x;
    int tx = tid & 15, ty = tid >> 4;
    int mA = tid >> 2, kA = (tid & 3) * 4;   // A: 64 rows x 4-wide k chunk
    int kB = tid >> 4, nB = (tid & 15) * 4;  // B: 16 k rows x 64 n

    float acc[4][4] = {};

    for (int k0 = 0; k0 < Cz; k0 += 16) {
        float4 av = *(const float4*)&A[(size_t)(bm + mA) * Cz + k0 + kA];
        As[kA + 0][mA] = av.x; As[kA + 1][mA] = av.y;
        As[kA + 2][mA] = av.z; As[kA + 3][mA] = av.w;
        *(float4*)&Bs[kB][nB] =
            *(const float4*)&Bm[(size_t)(k0 + kB) * HWz + bn + nB];
        __syncthreads();
        #pragma unroll
        for (int kk = 0; kk < 16; kk++) {
            float4 ra = *(const float4*)&As[kk][ty * 4];
            float4 rb = *(const float4*)&Bs[kk][tx * 4];
            float a_[4] = {ra.x, ra.y, ra.z, ra.w};
            float b_[4] = {rb.x, rb.y, rb.z, rb.w};
            #pragma unroll
            for (int i = 0; i < 4; i++)
                #pragma unroll
                for (int j = 0; j < 4; j++)
                    acc[i][j] += a_[i] * b_[j];
        }
        __syncthreads();
    }

    #pragma unroll
    for (int i = 0; i < 4; i++) {
        float bias = d_bfin[b][bm + ty * 4 + i];
        float4 v = make_float4(acc[i][0] + bias, acc[i][1] + bias,
                               acc[i][2] + bias, acc[i][3] + bias);
        *(float4*)&Cm[(size_t)(bm + ty * 4 + i) * HWz + bn + tx * 4] = v;
    }
}

// ---------------------------------------------------------------------------
extern "C" void kernel_launch(void* const* d_in, const int* in_sizes, int n_in,
                              void* d_out, int out_size) {
    const float* feature = (const float*)d_in[0];
    const float* m       = (const float*)d_in[1];
    const float* w_feat  = (const float*)d_in[2];
    const float* gf      = (const float*)d_in[3];
    const float* bf      = (const float*)d_in[4];
    const float* mf      = (const float*)d_in[5];
    const float* vf      = (const float*)d_in[6];
    const float* w_out   = (const float*)d_in[7];
    const float* go      = (const float*)d_in[8];
    const float* bo      = (const float*)d_in[9];
    const float* mo      = (const float*)d_in[10];
    const float* vo      = (const float*)d_in[11];
    float* out = (float*)d_out;

    k_masks<<<Bz, 256>>>(m);
    k_mid<<<dim3(Cz, Bz), 256>>>(feature);
    k_prep<<<Bz, 256>>>(w_feat, gf, bf, mf, vf, w_out, go, bo, mo, vo);
    k_gemm<<<dim3(HWz / 64, Cz / 64, Bz), 256>>>(feature, out);
}

// round 3
// speedup vs baseline: 1.4782x; 1.4782x over previous
#include <cuda_runtime.h>
#include <cuda_bf16.h>
#include <cstdint>

#define BN_EPS 1e-5f
#define Bz 8
#define Cz 256
#define Hz 128
#define Wz 128
#define HWz 16384

// GEMM tiling
#define BM 128
#define BN 128
#define BK 32

// Scratch (no allocations allowed -> device globals)
__device__ float d_masks[Bz][2][HWz];            // er, di
__device__ float d_mid[Bz][3][Cz];               // mid[b,k,c]
__device__ __nv_bfloat16 d_Whi[Bz][Cz * Cz];     // Wfin hi (bf16, [o][c])
__device__ __nv_bfloat16 d_Wlo[Bz][Cz * Cz];     // Wfin lo
__device__ float d_bfin[Bz][Cz];                 // effective per-batch bias

// ---------------------------------------------------------------------------
// K1: threshold + 4x4 erosion/dilation (SAME, pad lo=1 hi=2, border-neutral)
// ---------------------------------------------------------------------------
__global__ void k_masks(const float* __restrict__ m) {
    int b = blockIdx.x;
    __shared__ unsigned char z[HWz];
    const float* mb = m + (size_t)b * HWz;
    for (int i = threadIdx.x; i < HWz; i += blockDim.x)
        z[i] = (fmaxf(mb[i], 0.0f) > 0.3f) ? 1 : 0;
    __syncthreads();
    for (int i = threadIdx.x; i < HWz; i += blockDim.x) {
        int h = i >> 7, w = i & 127;
        int er = 1, di = 0;
        #pragma unroll
        for (int dh = -1; dh <= 2; dh++) {
            int hh = h + dh;
            if (hh < 0 || hh >= Hz) continue;
            #pragma unroll
            for (int dw = -1; dw <= 2; dw++) {
                int ww = w + dw;
                if (ww < 0 || ww >= Wz) continue;
                int v = z[(hh << 7) + ww];
                er &= v; di |= v;
            }
        }
        d_masks[b][0][i] = (float)er;
        d_masks[b][1][i] = (float)di;
    }
}

// ---------------------------------------------------------------------------
// K2: mid[b,k,c] reductions (as in R1)
// ---------------------------------------------------------------------------
__global__ void k_mid(const float* __restrict__ feature) {
    int c = blockIdx.x, b = blockIdx.y;
    const float4* f  = (const float4*)(feature + ((size_t)b * Cz + c) * HWz);
    const float4* er = (const float4*)d_masks[b][0];
    const float4* di = (const float4*)d_masks[b][1];
    float ae = 0.f, ad = 0.f, as = 0.f;
    for (int i = threadIdx.x; i < HWz / 4; i += blockDim.x) {
        float4 fv = f[i], ev = er[i], dv = di[i];
        ae += fv.x * ev.x + fv.y * ev.y + fv.z * ev.z + fv.w * ev.w;
        ad += fv.x * dv.x + fv.y * dv.y + fv.z * dv.z + fv.w * dv.w;
        as += fv.x + fv.y + fv.z + fv.w;
    }
    #pragma unroll
    for (int off = 16; off; off >>= 1) {
        ae += __shfl_down_sync(0xffffffffu, ae, off);
        ad += __shfl_down_sync(0xffffffffu, ad, off);
        as += __shfl_down_sync(0xffffffffu, as, off);
    }
    __shared__ float red[3][8];
    int lane = threadIdx.x & 31, wid = threadIdx.x >> 5;
    if (lane == 0) { red[0][wid] = ae; red[1][wid] = ad; red[2][wid] = as; }
    __syncthreads();
    if (threadIdx.x == 0) {
        float e = 0.f, d = 0.f, s = 0.f;
        #pragma unroll
        for (int i = 0; i < 8; i++) { e += red[0][i]; d += red[1][i]; s += red[2][i]; }
        d_mid[b][0][c] = e;
        d_mid[b][1][c] = s - d;
        d_mid[b][2][c] = d - e;
    }
}

// ---------------------------------------------------------------------------
// K3: build per-batch effective weight (bf16 hi/lo) and bias
// ---------------------------------------------------------------------------
__global__ void k_prep(const float* __restrict__ w_feat,
                       const float* __restrict__ gf, const float* __restrict__ bf,
                       const float* __restrict__ mf, const float* __restrict__ vf,
                       const float* __restrict__ w_out,
                       const float* __restrict__ go, const float* __restrict__ bo,
                       const float* __restrict__ mo, const float* __restrict__ vo) {
    int b = blockIdx.x, t = threadIdx.x;  // 256 threads
    __shared__ float midS[3][Cz], vS[3][Cz], w2m[Cz][3];
    __shared__ float sfS[Cz], shfS[Cz], soS[Cz], constS[3];

    #pragma unroll
    for (int k = 0; k < 3; k++) midS[k][t] = d_mid[b][k][t];
    float sf = gf[t] * rsqrtf(vf[t] + BN_EPS);
    sfS[t] = sf;
    shfS[t] = bf[t] - mf[t] * sf;
    float so = go[t] * rsqrtf(vo[t] + BN_EPS);
    soS[t] = so;
    float sho = bo[t] - mo[t] * so;
    __syncthreads();

    {
        float v0 = 0.f, v1 = 0.f, v2 = 0.f;
        for (int o = 0; o < Cz; o++) {
            float w = w_feat[o * Cz + t] * sfS[o];
            v0 += midS[0][o] * w;
            v1 += midS[1][o] * w;
            v2 += midS[2][o] * w;
        }
        vS[0][t] = v0; vS[1][t] = v1; vS[2][t] = v2;
    }
    if (t < 3) {
        float cs = 0.f;
        for (int o = 0; o < Cz; o++) cs += midS[t][o] * shfS[o];
        constS[t] = cs;
    }
    {
        float a0 = 0.f, a1 = 0.f, a2 = 0.f;
        const float* wr = w_out + (size_t)t * (2 * Cz) + Cz;
        for (int c = 0; c < Cz; c++) {
            float w = wr[c];
            a0 += w * midS[0][c];
            a1 += w * midS[1][c];
            a2 += w * midS[2][c];
        }
        w2m[t][0] = a0; w2m[t][1] = a1; w2m[t][2] = a2;
    }
    __syncthreads();

    d_bfin[b][t] = so * (w2m[t][0] * constS[0] + w2m[t][1] * constS[1] +
                         w2m[t][2] * constS[2]) + sho;

    for (int i = t; i < Cz * Cz; i += 256) {
        int o = i >> 8, c = i & 255;
        float val = w_out[(size_t)o * (2 * Cz) + c]
                  + w2m[o][0] * vS[0][c] + w2m[o][1] * vS[1][c] + w2m[o][2] * vS[2][c];
        val *= soS[o];
        __nv_bfloat16 hi = __float2bfloat16(val);
        d_Whi[b][i] = hi;
        d_Wlo[b][i] = __float2bfloat16(val - __bfloat162float(hi));
    }
}

// ---------------------------------------------------------------------------
// K4: mma.sync bf16 hi/lo GEMM: out[b] = Wfin[b] @ feature[b] + bfin[b]
//     BM=128, BN=128, BK=32; 8 warps (2m x 4n), warp tile 64x32; 3-term hi/lo
// smem: A [128 rows][pitch 80B] hi+lo = 20480; B [32 rows][pitch 272B] hi+lo = 17408
// ---------------------------------------------------------------------------
#define A_PITCH 80
#define B_PITCH 272
#define SA_HI 0
#define SA_LO (128 * A_PITCH)
#define SB_HI (2 * 128 * A_PITCH)
#define SB_LO (2 * 128 * A_PITCH + 32 * B_PITCH)
#define SM_TOT (2 * 128 * A_PITCH + 2 * 32 * B_PITCH)

__device__ __forceinline__ uint32_t smem_u32(const void* p) {
    uint32_t a;
    asm("{ .reg .u64 t; cvta.to.shared.u64 t, %1; cvt.u32.u64 %0, t; }"
        : "=r"(a) : "l"(p));
    return a;
}

#define LDSM_X4(r0, r1, r2, r3, addr) \
    asm volatile("ldmatrix.sync.aligned.m8n8.x4.shared.b16 {%0,%1,%2,%3}, [%4];" \
                 : "=r"(r0), "=r"(r1), "=r"(r2), "=r"(r3) : "r"(addr))
#define LDSM_X2T(r0, r1, addr) \
    asm volatile("ldmatrix.sync.aligned.m8n8.x2.trans.shared.b16 {%0,%1}, [%2];" \
                 : "=r"(r0), "=r"(r1) : "r"(addr))
#define MMA_BF16(d, a, b0, b1) \
    asm volatile("mma.sync.aligned.m16n8k16.row.col.f32.bf16.bf16.f32 " \
                 "{%0,%1,%2,%3},{%4,%5,%6,%7},{%8,%9},{%0,%1,%2,%3};" \
                 : "+f"((d)[0]), "+f"((d)[1]), "+f"((d)[2]), "+f"((d)[3]) \
                 : "r"((a)[0]), "r"((a)[1]), "r"((a)[2]), "r"((a)[3]), \
                   "r"(b0), "r"(b1))

__device__ __forceinline__ uint32_t pack_hi(float x, float y) {
    return ((uint32_t)__bfloat16_as_ushort(__float2bfloat16(y)) << 16) |
           (uint32_t)__bfloat16_as_ushort(__float2bfloat16(x));
}
__device__ __forceinline__ uint32_t pack_lo(float x, float y) {
    float xl = x - __bfloat162float(__float2bfloat16(x));
    float yl = y - __bfloat162float(__float2bfloat16(y));
    return ((uint32_t)__bfloat16_as_ushort(__float2bfloat16(yl)) << 16) |
           (uint32_t)__bfloat16_as_ushort(__float2bfloat16(xl));
}

__global__ __launch_bounds__(256, 2) void k_gemm(const float* __restrict__ feature,
                                                 float* __restrict__ out) {
    __shared__ __align__(16) unsigned char sm[SM_TOT];
    const uint32_t smb = smem_u32(sm);

    const int tid = threadIdx.x, lane = tid & 31, wid = tid >> 5;
    const int b = blockIdx.z;
    const int m0 = blockIdx.y * BM;
    const int n0 = blockIdx.x * BN;
    const int wm = (wid >> 2) * 64;   // 2 m-warps
    const int wn = (wid & 3) * 32;    // 4 n-warps

    float acc[4][4][4];
    #pragma unroll
    for (int i = 0; i < 4; i++)
        #pragma unroll
        for (int j = 0; j < 4; j++)
            #pragma unroll
            for (int q = 0; q < 4; q++) acc[i][j][q] = 0.f;

    // staging indices
    const int arow = tid >> 1, aq = tid & 1;              // A: row, 2 uint4 each
    const int brow = tid >> 3, bseg = tid & 7;            // B: row, 16 floats each

    const __nv_bfloat16* AhiG = d_Whi[b] + (size_t)(m0 + arow) * Cz;
    const __nv_bfloat16* AloG = d_Wlo[b] + (size_t)(m0 + arow) * Cz;
    const float* Bg = feature + ((size_t)b * Cz + brow) * HWz + n0 + bseg * 16;

    // frag lane addressing
    const int lr = lane & 15;
    const uint32_t aColByte = (lane >> 4) * 16;

    for (int k0 = 0; k0 < Cz; k0 += BK) {
        // ---- stage A (bf16 already) ----
        {
            const uint4* srcH = (const uint4*)(AhiG + k0 + aq * 16);
            const uint4* srcL = (const uint4*)(AloG + k0 + aq * 16);
            uint4 h0 = srcH[0], h1 = srcH[1];
            uint4 l0 = srcL[0], l1 = srcL[1];
            uint32_t dst = arow * A_PITCH + aq * 32;
            *(uint4*)(sm + SA_HI + dst) = h0;
            *(uint4*)(sm + SA_HI + dst + 16) = h1;
            *(uint4*)(sm + SA_LO + dst) = l0;
            *(uint4*)(sm + SA_LO + dst + 16) = l1;
        }
        // ---- stage B (fp32 -> bf16 hi/lo) ----
        {
            const float* src = Bg + (size_t)k0 * HWz;
            uint32_t dst = brow * B_PITCH + bseg * 32;
            #pragma unroll
            for (int f = 0; f < 4; f++) {
                float4 v = *(const float4*)(src + f * 4);
                uint2 hv = make_uint2(pack_hi(v.x, v.y), pack_hi(v.z, v.w));
                uint2 lv = make_uint2(pack_lo(v.x, v.y), pack_lo(v.z, v.w));
                *(uint2*)(sm + SB_HI + dst + f * 8) = hv;
                *(uint2*)(sm + SB_LO + dst + f * 8) = lv;
            }
        }
        __syncthreads();

        #pragma unroll
        for (int ks = 0; ks < 2; ks++) {
            uint32_t a_hi[4][4], a_lo[4][4], b_hi[4][2], b_lo[4][2];
            #pragma unroll
            for (int i = 0; i < 4; i++) {
                uint32_t ad = smb + (uint32_t)((wm + 16 * i + lr) * A_PITCH +
                                               ks * 32) + aColByte;
                LDSM_X4(a_hi[i][0], a_hi[i][1], a_hi[i][2], a_hi[i][3], ad + SA_HI);
                LDSM_X4(a_lo[i][0], a_lo[i][1], a_lo[i][2], a_lo[i][3], ad + SA_LO);
            }
            #pragma unroll
            for (int j = 0; j < 4; j++) {
                uint32_t bd = smb + (uint32_t)((ks * 16 + lr) * B_PITCH +
                                               (wn + 8 * j) * 2);
                LDSM_X2T(b_hi[j][0], b_hi[j][1], bd + SB_HI);
                LDSM_X2T(b_lo[j][0], b_lo[j][1], bd + SB_LO);
            }
            #pragma unroll
            for (int i = 0; i < 4; i++)
                #pragma unroll
                for (int j = 0; j < 4; j++) {
                    MMA_BF16(acc[i][j], a_hi[i], b_hi[j][0], b_hi[j][1]);
                    MMA_BF16(acc[i][j], a_hi[i], b_lo[j][0], b_lo[j][1]);
                    MMA_BF16(acc[i][j], a_lo[i], b_hi[j][0], b_hi[j][1]);
                }
        }
        __syncthreads();
    }

    // ---- epilogue ----
    const int g = lane >> 2, t4 = lane & 3;
    #pragma unroll
    for (int i = 0; i < 4; i++) {
        int ch0 = m0 + wm + 16 * i + g;
        float bia0 = d_bfin[b][ch0];
        float bia1 = d_bfin[b][ch0 + 8];
        float* r0 = out + ((size_t)b * Cz + ch0) * HWz + n0 + wn + 2 * t4;
        float* r1 = r0 + (size_t)8 * HWz;
        #pragma unroll
        for (int j = 0; j < 4; j++) {
            *(float2*)(r0 + 8 * j) = make_float2(acc[i][j][0] + bia0,
                                                 acc[i][j][1] + bia0);
            *(float2*)(r1 + 8 * j) = make_float2(acc[i][j][2] + bia1,
                                                 acc[i][j][3] + bia1);
        }
    }
}

// ---------------------------------------------------------------------------
extern "C" void kernel_launch(void* const* d_in, const int* in_sizes, int n_in,
                              void* d_out, int out_size) {
    const float* feature = (const float*)d_in[0];
    const float* m       = (const float*)d_in[1];
    const float* w_feat  = (const float*)d_in[2];
    const float* gf      = (const float*)d_in[3];
    const float* bf      = (const float*)d_in[4];
    const float* mf      = (const float*)d_in[5];
    const float* vf      = (const float*)d_in[6];
    const float* w_out   = (const float*)d_in[7];
    const float* go      = (const float*)d_in[8];
    const float* bo      = (const float*)d_in[9];
    const float* mo      = (const float*)d_in[10];
    const float* vo      = (const float*)d_in[11];
    float* out = (float*)d_out;

    k_masks<<<Bz, 256>>>(m);
    k_mid<<<dim3(Cz, Bz), 256>>>(feature);
    k_prep<<<Bz, 256>>>(w_feat, gf, bf, mf, vf, w_out, go, bo, mo, vo);
    k_gemm<<<dim3(HWz / BN, Cz / BM, Bz), 256>>>(feature, out);
}